// round 7
// baseline (speedup 1.0000x reference)
#include <cuda_runtime.h>

// ---------------------------------------------------------------------------
// IMEX-ETD: CG-solve (I - DT*D*Lap_neumann) x = u, then pointwise ETD update.
// Round 7: p/delta streams eliminated via CG dot recurrences:
//   pAp' = (rn,w) - 2b*rs'/a + b^2*pAp ;  sAs' = (w,w) + 2b*(w,s) + b^2*sAs
// (w = A r_new, computed by Laplacian linearity; all new dots register-local).
// x reconstructed in the epilogue as u + sum_m c_m * r_m over saved r
// generations (c_m from the alpha/beta scalar history).
// Pass traffic: 5N (was 9N). One fused pass + one grid barrier per alpha-step.
// ---------------------------------------------------------------------------

#define N_ELEM   8388608     // 8 * 1 * 1024 * 1024
#define N4       2097152     // N_ELEM / 4
#define ROW4     256         // float4s per row
#define GBLK     152
#define TBLK     1024
#define NTHREADS (GBLK * TBLK)

#define DT_C     0.1f
#define CG_TAU   0.015       // stop at ||r|| <= tau
#define NGEN     8           // max r generations kept (3 expected)

__device__ float g_rg[NGEN][N_ELEM];   // r generations
__device__ float g_s0[N_ELEM];         // Ap ping
__device__ float g_s1[N_ELEM];         // Ap pong

__device__ double g_pd[2][3][GBLK];    // per-pass dot partials (parity x 3)
__device__ double g_pi[3][GBLK];       // init partials: rs, pAp, sAs

__device__ unsigned g_cnt = 0;
__device__ volatile unsigned g_gen = 0;

// ---------------------------------------------------------------------------

__device__ __forceinline__ void grid_bar() {
    __syncthreads();
    __threadfence();                       // release
    if (threadIdx.x == 0) {
        unsigned snap = g_gen;
        unsigned arrived = atomicAdd(&g_cnt, 1u);
        if (arrived == GBLK - 1) {
            g_cnt = 0;
            __threadfence();
            g_gen = snap + 1u;
        } else {
            while (g_gen == snap) { }
        }
    }
    __syncthreads();
    __threadfence();                       // acquire (CCTL.IVALL)
}

__device__ __forceinline__ double block_reduce_d(double v) {
    __shared__ double sh[32];
    int lane = threadIdx.x & 31;
    int w    = threadIdx.x >> 5;
#pragma unroll
    for (int o = 16; o; o >>= 1) v += __shfl_down_sync(0xffffffffu, v, o);
    if (lane == 0) sh[w] = v;
    __syncthreads();
    if (w == 0) {
        v = sh[lane];
#pragma unroll
        for (int o = 16; o; o >>= 1) v += __shfl_down_sync(0xffffffffu, v, o);
    }
    return v;
}

__device__ __forceinline__ double sum_partials_d(const double* a) {
    __shared__ double tot;
    int t = threadIdx.x;
    if (t < 32) {
        double s = 0.0;
#pragma unroll
        for (int j = t; j < GBLK; j += 32) s += a[j];
#pragma unroll
        for (int o = 16; o; o >>= 1) s += __shfl_down_sync(0xffffffffu, s, o);
        if (t == 0) tot = s;
    }
    __syncthreads();
    return tot;
}

// ---------------------------------------------------------------------------

__device__ __forceinline__ float dot4f(float4 a, float4 b) {
    return fmaf(a.x, b.x, fmaf(a.y, b.y, fmaf(a.z, b.z, a.w * b.w)));
}

__device__ __forceinline__ float4 lap_mk(float4 c, float4 t, float4 b,
                                         float lf, float rt) {
    float4 L;
    L.x = fmaf(-4.0f, c.x, (lf  + c.y) + (t.x + b.x));
    L.y = fmaf(-4.0f, c.y, (c.x + c.z) + (t.y + b.y));
    L.z = fmaf(-4.0f, c.z, (c.y + c.w) + (t.z + b.z));
    L.w = fmaf(-4.0f, c.w, (c.z + rt ) + (t.w + b.w));
    return L;
}

__device__ __forceinline__ float4 r0_vec(const float* __restrict__ u,
                                         const float* __restrict__ D, int j) {
    int x4 = j & (ROW4 - 1);
    int y  = (j >> 8) & 1023;
    const float4* u4 = (const float4*)u;
    float4 c = __ldg(u4 + j);
    float4 t = (y > 0)    ? __ldg(u4 + (j - ROW4)) : c;
    float4 b = (y < 1023) ? __ldg(u4 + (j + ROW4)) : c;
    float lf = (x4 > 0)        ? __ldg(u + 4*j - 1) : c.x;
    float rt = (x4 < ROW4 - 1) ? __ldg(u + 4*j + 4) : c.w;
    float4 dd = __ldg(((const float4*)D) + j);
    float4 lp = lap_mk(c, t, b, lf, rt);
    float4 rv;
    rv.x = DT_C * dd.x * lp.x;
    rv.y = DT_C * dd.y * lp.y;
    rv.z = DT_C * dd.z * lp.z;
    rv.w = DT_C * dd.w * lp.w;
    return rv;
}

__device__ __forceinline__ float r0_scalar(const float* __restrict__ u,
                                           const float* __restrict__ D, int i) {
    int x = i & 1023;
    int y = (i >> 10) & 1023;
    float c = __ldg(&u[i]);
    float l = (x > 0)    ? __ldg(&u[i - 1])    : c;
    float r = (x < 1023) ? __ldg(&u[i + 1])    : c;
    float t = (y > 0)    ? __ldg(&u[i - 1024]) : c;
    float b = (y < 1023) ? __ldg(&u[i + 1024]) : c;
    return DT_C * __ldg(&D[i]) * fmaf(-4.0f, c, (l + r) + (t + b));
}

// ---------------------------------------------------------------------------
// Fused pass (5N traffic): r_new = r - a*s ; w = A r_new (linearity);
// s_new = w + b*s. Dots: (rn,w), (w,w), (w,s) register-local.

__device__ __forceinline__ void fused_pass(
    const float4* __restrict__ rsrc4,
    const float4* __restrict__ ssrc4,
    float4*       __restrict__ rdst4,
    float4*       __restrict__ sdst4,
    const float4* __restrict__ D4,
    float alpha_f, float beta_f, int tid,
    double& rw_o, double& ww_o, double& ws_o)
{
    const float* __restrict__ rs_f = (const float*)rsrc4;
    const float* __restrict__ ss_f = (const float*)ssrc4;
    double rw = 0.0, ww = 0.0, ws = 0.0;

    for (int j = tid; j < N4; j += NTHREADS) {
        int x4 = j & (ROW4 - 1);
        int y  = (j >> 8) & 1023;
        bool hT = (y > 0), hB = (y < 1023);
        bool hL = (x4 > 0), hR = (x4 < ROW4 - 1);

        float4 rc = rsrc4[j];
        float4 sc = ssrc4[j];
        float4 rT = hT ? rsrc4[j - ROW4] : rc;
        float4 rB = hB ? rsrc4[j + ROW4] : rc;
        float4 sT = hT ? ssrc4[j - ROW4] : sc;
        float4 sB = hB ? ssrc4[j + ROW4] : sc;
        float rL = hL ? rs_f[4*j - 1] : rc.x;
        float rR = hR ? rs_f[4*j + 4] : rc.w;
        float sL = hL ? ss_f[4*j - 1] : sc.x;
        float sR = hR ? ss_f[4*j + 4] : sc.w;
        float4 dd = __ldg(D4 + j);

        float4 lr = lap_mk(rc, rT, rB, rL, rR);
        float4 ls = lap_mk(sc, sT, sB, sL, sR);

        // r_new = r - a*s
        float4 rn;
        rn.x = fmaf(-alpha_f, sc.x, rc.x);
        rn.y = fmaf(-alpha_f, sc.y, rc.y);
        rn.z = fmaf(-alpha_f, sc.z, rc.z);
        rn.w = fmaf(-alpha_f, sc.w, rc.w);

        // w = A r_new = r_new - DT*D*(lap r - a*lap s)
        float4 w;
        {
            float lx = fmaf(-alpha_f, ls.x, lr.x);
            float ly = fmaf(-alpha_f, ls.y, lr.y);
            float lz = fmaf(-alpha_f, ls.z, lr.z);
            float lw = fmaf(-alpha_f, ls.w, lr.w);
            w.x = fmaf(-DT_C * dd.x, lx, rn.x);
            w.y = fmaf(-DT_C * dd.y, ly, rn.y);
            w.z = fmaf(-DT_C * dd.z, lz, rn.z);
            w.w = fmaf(-DT_C * dd.w, lw, rn.w);
        }

        // s_new = w + b*s
        float4 sn;
        sn.x = fmaf(beta_f, sc.x, w.x);
        sn.y = fmaf(beta_f, sc.y, w.y);
        sn.z = fmaf(beta_f, sc.z, w.z);
        sn.w = fmaf(beta_f, sc.w, w.w);

        rdst4[j] = rn;
        sdst4[j] = sn;

        rw += (double)dot4f(rn, w);
        ww += (double)dot4f(w,  w);
        ws += (double)dot4f(w,  sc);
    }
    rw_o = rw; ww_o = ww; ws_o = ws;
}

// ---------------------------------------------------------------------------

__global__ void __launch_bounds__(TBLK, 1)
imexetd_cg_kernel(const float* __restrict__ u,
                  const float* __restrict__ D,
                  const float* __restrict__ kp,
                  const float* __restrict__ aCp,
                  const float* __restrict__ Ctp,
                  float* __restrict__ out)
{
    const int tid = blockIdx.x * TBLK + threadIdx.x;
    const float4* D4 = (const float4*)D;

    // ---- fused init: r0 = DT*D*lap(u); s0 = A r0; rs, pAp, sAs ----
    {
        float4* __restrict__ r4w = (float4*)g_rg[0];
        float4* __restrict__ s4w = (float4*)g_s0;
        double ars = 0.0, apa = 0.0, asa = 0.0;
        for (int j = tid; j < N4; j += NTHREADS) {
            int x4 = j & (ROW4 - 1);
            int y  = (j >> 8) & 1023;
            float4 rc = r0_vec(u, D, j);
            float4 rT = (y > 0)    ? r0_vec(u, D, j - ROW4) : rc;
            float4 rB = (y < 1023) ? r0_vec(u, D, j + ROW4) : rc;
            float  rL = (x4 > 0)        ? r0_scalar(u, D, 4*j - 1) : rc.x;
            float  rR = (x4 < ROW4 - 1) ? r0_scalar(u, D, 4*j + 4) : rc.w;
            float4 dd = __ldg(D4 + j);
            float4 lp = lap_mk(rc, rT, rB, rL, rR);
            float4 Av;
            Av.x = fmaf(-DT_C * dd.x, lp.x, rc.x);
            Av.y = fmaf(-DT_C * dd.y, lp.y, rc.y);
            Av.z = fmaf(-DT_C * dd.z, lp.z, rc.z);
            Av.w = fmaf(-DT_C * dd.w, lp.w, rc.w);
            r4w[j] = rc;
            s4w[j] = Av;
            ars += (double)dot4f(rc, rc);
            apa += (double)dot4f(rc, Av);
            asa += (double)dot4f(Av, Av);
        }
        double v;
        v = block_reduce_d(ars);
        if (threadIdx.x == 0) g_pi[0][blockIdx.x] = v;
        __syncthreads();
        v = block_reduce_d(apa);
        if (threadIdx.x == 0) g_pi[1][blockIdx.x] = v;
        __syncthreads();
        v = block_reduce_d(asa);
        if (threadIdx.x == 0) g_pi[2][blockIdx.x] = v;
    }
    grid_bar();
    double rs  = sum_partials_d(g_pi[0]);
    double pAp = sum_partials_d(g_pi[1]);
    double sAs = sum_partials_d(g_pi[2]);

    // ---- CG alpha-steps ----
    float alph[NGEN];
    float bet [NGEN];
    int it = 0;
    int npass = 0;
    int scur = 0;

    for (;;) {
        float alpha_f = (float)(rs / (pAp + 1e-300));
        double ad = (double)alpha_f;
        double rs_new = rs - 2.0 * ad * pAp + ad * ad * sAs;
        if (rs_new < 0.0) rs_new = 0.0;
        alph[it] = alpha_f;
        it++;
        if (sqrt(rs_new) < CG_TAU || it >= NGEN) break;

        float beta_f = (float)(rs_new / (rs + 1e-300));
        bet[it] = beta_f;

        double rw, ww, ws;
        fused_pass((const float4*)g_rg[npass],
                   (const float4*)(scur ? g_s1 : g_s0),
                   (float4*)g_rg[npass + 1],
                   (float4*)(scur ? g_s0 : g_s1),
                   D4, alpha_f, beta_f, tid, rw, ww, ws);
        int par = (npass + 1) & 1;
        {
            double v;
            v = block_reduce_d(rw);
            if (threadIdx.x == 0) g_pd[par][0][blockIdx.x] = v;
            __syncthreads();
            v = block_reduce_d(ww);
            if (threadIdx.x == 0) g_pd[par][1][blockIdx.x] = v;
            __syncthreads();
            v = block_reduce_d(ws);
            if (threadIdx.x == 0) g_pd[par][2][blockIdx.x] = v;
        }
        grid_bar();
        double RW = sum_partials_d(g_pd[par][0]);
        double WW = sum_partials_d(g_pd[par][1]);
        double WS = sum_partials_d(g_pd[par][2]);

        double bd = (double)beta_f;
        // pAp_new = (rn,w) - 2b*rs_new/a + b^2*pAp
        pAp = RW - 2.0 * bd * rs_new / ad + bd * bd * pAp;
        // sAs_new = (w,w) + 2b*(w,s_old) + b^2*sAs
        sAs = WW + 2.0 * bd * WS + bd * bd * sAs;
        rs  = rs_new;
        npass++;
        scur ^= 1;
    }

    // ---- coefficients: u_tilde = u + sum_{m<it} c_m * r_m ----
    // p_0 = r_0, p_k = r_k + b_k p_{k-1};  c_m = a_m + b_{m+1} c_{m+1}
    float c[NGEN];
    c[it - 1] = alph[it - 1];
    for (int m = it - 2; m >= 0; m--)
        c[m] = fmaf(bet[m + 1], c[m + 1], alph[m]);

    // ---- epilogue: reconstruct u_tilde, ETD rational update, clip ----
    float kk = __ldg(&kp[0]);
    float a  = kk - __ldg(&aCp[0]) * __ldg(&Ctp[0]);
    float bc = kk;                               // k / K_CAP, K_CAP = 1
    float adc = fminf(fmaxf(a * DT_C, -60.0f), 60.0f);
    float e   = expf(adc);
    float em1 = e - 1.0f;

    const float4* __restrict__ u4 = (const float4*)u;
    float4* __restrict__ o4 = (float4*)out;
    const int g = it;

    for (int j = tid; j < N4; j += NTHREADS) {
        float4 ut = __ldg(u4 + j);
        for (int m = 0; m < g; m++) {
            float4 rv = ((const float4*)g_rg[m])[j];
            float cm = c[m];
            ut.x = fmaf(cm, rv.x, ut.x);
            ut.y = fmaf(cm, rv.y, ut.y);
            ut.z = fmaf(cm, rv.z, ut.z);
            ut.w = fmaf(cm, rv.w, ut.w);
        }

        float4 un;
        {
            float num = a * ut.x * e;
            float den = fmaf(bc * ut.x, em1, a);
            un.x = (fabsf(den) > 1e-12f) ? (num / den) : ut.x;
            num = a * ut.y * e;
            den = fmaf(bc * ut.y, em1, a);
            un.y = (fabsf(den) > 1e-12f) ? (num / den) : ut.y;
            num = a * ut.z * e;
            den = fmaf(bc * ut.z, em1, a);
            un.z = (fabsf(den) > 1e-12f) ? (num / den) : ut.z;
            num = a * ut.w * e;
            den = fmaf(bc * ut.w, em1, a);
            un.w = (fabsf(den) > 1e-12f) ? (num / den) : ut.w;
        }
        un.x = fminf(fmaxf(un.x, 0.0f), 1.0f);
        un.y = fminf(fmaxf(un.y, 0.0f), 1.0f);
        un.z = fminf(fmaxf(un.z, 0.0f), 1.0f);
        un.w = fminf(fmaxf(un.w, 0.0f), 1.0f);
        o4[j] = un;
    }
}

// ---------------------------------------------------------------------------

extern "C" void kernel_launch(void* const* d_in, const int* in_sizes, int n_in,
                              void* d_out, int out_size)
{
    const float* u   = (const float*)d_in[0];
    const float* D   = (const float*)d_in[1];
    const float* k   = (const float*)d_in[2];
    const float* aC  = (const float*)d_in[3];
    const float* C_t = (const float*)d_in[4];
    float* out = (float*)d_out;

    imexetd_cg_kernel<<<GBLK, TBLK>>>(u, D, k, aC, C_t, out);
}